// round 3
// baseline (speedup 1.0000x reference)
#include <cuda_runtime.h>
#include <cuda_fp16.h>
#include <stdint.h>

#define M_DIM 2048
#define N_DIM 11008
#define K_DIM 4096

#define BM 128
#define BN 256
#define BK 32
#define KT (K_DIM / BK)   // 128
#define LDA 40            // halves per A row (pad 32+8)
#define LDB 40
#define A_SZ (BM * LDA * 2)          // 10240 B
#define B_SZ (BN * LDB * 2)          // 20480 B
#define STAGE_SZ (A_SZ + B_SZ)       // 30720 B
#define SMEM_TOTAL (2 * STAGE_SZ)    // 61440 B

__device__ __half g_xh[(size_t)M_DIM * K_DIM];

// ---------------------------------------------------------------------------
__global__ void convert_x_kernel(const float* __restrict__ x) {
    size_t i = ((size_t)blockIdx.x * blockDim.x + threadIdx.x) * 8;
    float4 f0 = *(const float4*)(x + i);
    float4 f1 = *(const float4*)(x + i + 4);
    __half2 h01 = __floats2half2_rn(f0.x, f0.y);
    __half2 h23 = __floats2half2_rn(f0.z, f0.w);
    __half2 h45 = __floats2half2_rn(f1.x, f1.y);
    __half2 h67 = __floats2half2_rn(f1.z, f1.w);
    uint4 v;
    v.x = *(uint32_t*)&h01; v.y = *(uint32_t*)&h23;
    v.z = *(uint32_t*)&h45; v.w = *(uint32_t*)&h67;
    *(uint4*)(g_xh + i) = v;
}

// ---------------------------------------------------------------------------
__device__ __forceinline__ uint32_t smem_u32(const void* p) {
    return (uint32_t)__cvta_generic_to_shared(p);
}
__device__ __forceinline__ void ldsm_x4(uint32_t& r0, uint32_t& r1,
                                        uint32_t& r2, uint32_t& r3,
                                        uint32_t addr) {
    asm volatile("ldmatrix.sync.aligned.m8n8.x4.shared.b16 {%0,%1,%2,%3}, [%4];"
                 : "=r"(r0), "=r"(r1), "=r"(r2), "=r"(r3)
                 : "r"(addr));
}
__device__ __forceinline__ void mma_16816(float c[4], const uint32_t a[4],
                                          const uint32_t b[2]) {
    asm volatile(
        "mma.sync.aligned.m16n8k16.row.col.f32.f16.f16.f32 "
        "{%0,%1,%2,%3}, {%4,%5,%6,%7}, {%8,%9}, {%0,%1,%2,%3};"
        : "+f"(c[0]), "+f"(c[1]), "+f"(c[2]), "+f"(c[3])
        : "r"(a[0]), "r"(a[1]), "r"(a[2]), "r"(a[3]), "r"(b[0]), "r"(b[1]));
}
__device__ __forceinline__ void cp16(uint32_t dst, const void* src) {
    asm volatile("cp.async.ca.shared.global [%0], [%1], 16;"
                 :: "r"(dst), "l"(src) : "memory");
}

// ---------------------------------------------------------------------------
// out[m,n] = scale[n] * sum_k x[m,k]*(W_int[k,n]-zero[n]) + bias[n]
// block 128x256, 8 warps, warp tile 64x64
// ---------------------------------------------------------------------------
__global__ void __launch_bounds__(256, 1)
qgemm_kernel(const uint32_t* __restrict__ qw, const float* __restrict__ scales,
             const int* __restrict__ zeros, const float* __restrict__ bias,
             float* __restrict__ out) {
    extern __shared__ char smem[];
    const uint32_t sbase = smem_u32(smem);

    const int tid = threadIdx.x;
    const int lane = tid & 31;
    const int wid = tid >> 5;
    const int warp_m = wid & 1;   // 0..1 -> 64-row slabs
    const int warp_n = wid >> 1;  // 0..3 -> 64-col slabs
    const int bm0 = blockIdx.y * BM;
    const int bn0 = blockIdx.x * BN;

    // ---- A fill: cp.async, 2 x 16B per thread ----
    const int rowA = tid >> 1;          // 0..127
    const int cA = (tid & 1) * 2;       // 16B-chunk base (0 or 2)
    const __half* Ag = g_xh + (size_t)(bm0 + rowA) * K_DIM;

    // ---- B fill: thread owns column n, 8 packed words per k-tile ----
    const int n_loc = tid;              // 0..255
    const int stgB = (n_loc >> 3) & 7;  // phase stagger
    const uint32_t* Bg = qw + (size_t)bn0 + n_loc;
    const int zq = zeros[bn0 + n_loc];
    const __half2 zc = __half2half2(__float2half_rn(1024.0f + (float)zq));

    float acc[4][8][4];
#pragma unroll
    for (int mi = 0; mi < 4; mi++)
#pragma unroll
        for (int ni = 0; ni < 8; ni++)
#pragma unroll
            for (int t = 0; t < 4; t++) acc[mi][ni][t] = 0.0f;

    uint32_t br[8];

    // ---------------- prologue: stage 0 ----------------
    {
        char* As = smem;
        char* Bs = smem + A_SZ;
#pragma unroll
        for (int j = 0; j < 2; j++) {
            int c = cA + j;
            cp16(sbase + (uint32_t)(rowA * LDA + c * 8) * 2, Ag + c * 8);
        }
        asm volatile("cp.async.commit_group;" ::: "memory");
#pragma unroll
        for (int j = 0; j < 8; j++) {
            int jj = (j + stgB) & 7;
            uint32_t w = Bg[(size_t)jj * N_DIM];
            uint32_t lo = __byte_perm(w, 0x64646464u, 0x4140);
            uint32_t hi = __byte_perm(w, 0x64646464u, 0x4342);
            __half2 h0 = __hsub2(*(__half2*)&lo, zc);
            __half2 h1 = __hsub2(*(__half2*)&hi, zc);
            uint2 st; st.x = *(uint32_t*)&h0; st.y = *(uint32_t*)&h1;
            *(uint2*)(Bs + (n_loc * LDB + jj * 4) * 2) = st;
        }
        asm volatile("cp.async.wait_group 0;" ::: "memory");
        __syncthreads();
        (void)As;
    }

    int buf = 0;
#pragma unroll 1
    for (int kt = 0; kt < KT; kt++) {
        const int nb = buf ^ 1;
        // ---- prefetch next tile ----
        if (kt + 1 < KT) {
            const int k0 = (kt + 1) * BK;
#pragma unroll
            for (int j = 0; j < 2; j++) {
                int c = cA + j;
                cp16(sbase + (uint32_t)(nb * STAGE_SZ) +
                         (uint32_t)(rowA * LDA + c * 8) * 2,
                     Ag + k0 + c * 8);
            }
            asm volatile("cp.async.commit_group;" ::: "memory");
#pragma unroll
            for (int j = 0; j < 8; j++) {
                int jj = (j + stgB) & 7;
                br[j] = Bg[(size_t)((kt + 1) * 8 + jj) * N_DIM];
            }
        }

        // ---- compute current stage ----
        const uint32_t aB = sbase + (uint32_t)(buf * STAGE_SZ);
        const uint32_t bB = aB + A_SZ;
        const int g = lane >> 3, lr = lane & 7;
#pragma unroll
        for (int ks = 0; ks < 2; ks++) {
            uint32_t af[4][4];
#pragma unroll
            for (int mi = 0; mi < 4; mi++) {
                int row = warp_m * 64 + mi * 16 + (g & 1) * 8 + lr;
                int col = ks * 16 + (g >> 1) * 8;
                ldsm_x4(af[mi][0], af[mi][1], af[mi][2], af[mi][3],
                        aB + (uint32_t)(row * LDA + col) * 2);
            }
            uint32_t bf[8][2];
#pragma unroll
            for (int nj = 0; nj < 4; nj++) {
                int nrow = warp_n * 64 + nj * 16 + (g >> 1) * 8 + lr;
                int col = ks * 16 + (g & 1) * 8;
                uint32_t r0, r1, r2, r3;
                ldsm_x4(r0, r1, r2, r3, bB + (uint32_t)(nrow * LDB + col) * 2);
                bf[2 * nj][0] = r0; bf[2 * nj][1] = r1;
                bf[2 * nj + 1][0] = r2; bf[2 * nj + 1][1] = r3;
            }
#pragma unroll
            for (int ni = 0; ni < 8; ni++)
#pragma unroll
                for (int mi = 0; mi < 4; mi++)
                    mma_16816(acc[mi][ni], af[mi], bf[ni]);
        }

        // ---- store prefetched B, close the stage ----
        if (kt + 1 < KT) {
            char* Bs = smem + nb * STAGE_SZ + A_SZ;
#pragma unroll
            for (int j = 0; j < 8; j++) {
                int jj = (j + stgB) & 7;
                uint32_t w = br[j];
                uint32_t lo = __byte_perm(w, 0x64646464u, 0x4140);
                uint32_t hi = __byte_perm(w, 0x64646464u, 0x4342);
                __half2 h0 = __hsub2(*(__half2*)&lo, zc);
                __half2 h1 = __hsub2(*(__half2*)&hi, zc);
                uint2 st; st.x = *(uint32_t*)&h0; st.y = *(uint32_t*)&h1;
                *(uint2*)(Bs + (n_loc * LDB + jj * 4) * 2) = st;
            }
            asm volatile("cp.async.wait_group 0;" ::: "memory");
            __syncthreads();
        }
        buf ^= 1;
    }

    // ---------------- epilogue ----------------
    const int m0 = bm0 + warp_m * 64;
    const int n0w = bn0 + warp_n * 64;
    const int lr = lane >> 2;        // 0..7
    const int lc = (lane & 3) * 2;   // 0,2,4,6
#pragma unroll
    for (int ni = 0; ni < 8; ni++) {
        const int col = n0w + ni * 8 + lc;
        const float s0 = scales[col], s1 = scales[col + 1];
        const float b0 = bias[col], b1 = bias[col + 1];
#pragma unroll
        for (int mi = 0; mi < 4; mi++) {
            const int r0 = m0 + mi * 16 + lr;
            float2 v0 = make_float2(acc[mi][ni][0] * s0 + b0,
                                    acc[mi][ni][1] * s1 + b1);
            *(float2*)(out + (size_t)r0 * N_DIM + col) = v0;
            float2 v1 = make_float2(acc[mi][ni][2] * s0 + b0,
                                    acc[mi][ni][3] * s1 + b1);
            *(float2*)(out + (size_t)(r0 + 8) * N_DIM + col) = v1;
        }
    }
}

// ---------------------------------------------------------------------------
extern "C" void kernel_launch(void* const* d_in, const int* in_sizes, int n_in,
                              void* d_out, int out_size) {
    const float* x = (const float*)d_in[0];
    const uint32_t* qw = (const uint32_t*)d_in[1];
    const float* scales = (const float*)d_in[2];
    const int* zeros = (const int*)d_in[3];
    const float* bias = (const float*)d_in[4];
    float* out = (float*)d_out;

    convert_x_kernel<<<(M_DIM * K_DIM) / (256 * 8), 256>>>(x);

    cudaFuncSetAttribute(qgemm_kernel,
                         cudaFuncAttributeMaxDynamicSharedMemorySize, SMEM_TOTAL);
    dim3 grid(N_DIM / BN, M_DIM / BM);  // 43 x 16
    qgemm_kernel<<<grid, 256, SMEM_TOTAL>>>(qw, scales, zeros, bias, out);
}